// round 3
// baseline (speedup 1.0000x reference)
#include <cuda_runtime.h>
#include <cuda_bf16.h>
#include <cstdint>

// Problem constants
#define MTOK   65536      // B*T = 16*4096
#define IDIM   512
#define HDIM   1024
#define KSEL   256        // 2*CDIM

// ---------------------------------------------------------------------------
// Scratch: two ping-pong activation buffers, each [65536, 1024] fp32 (256 MB).
// __device__ globals (no runtime allocation — allocation guards are enforced).
// ---------------------------------------------------------------------------
__device__ float g_bufA[(size_t)MTOK * HDIM];
__device__ float g_bufB[(size_t)MTOK * HDIM];

// ---------------------------------------------------------------------------
// SGEMM: C[M,N] = act( A[M,K] @ W[K,N] + bias[N] ), optional mask-zeroing.
// BM=BN=128, BK=8, 256 threads, 8x8 per-thread microtile.
// All dims are multiples of the tile sizes (M=65536, N in {512,1024},
// K in {512,1024}) -> no bounds checks.
// ---------------------------------------------------------------------------
__global__ __launch_bounds__(256)
void sgemm_kernel(const float* __restrict__ A, const float* __restrict__ W,
                  const float* __restrict__ bias, const float* __restrict__ mask,
                  float* __restrict__ C, int M, int N, int K, int do_relu)
{
    __shared__ __align__(16) float As[8][132];   // transposed A tile, padded
    __shared__ __align__(16) float Bs[8][132];   // B tile, padded

    const int tid = threadIdx.x;
    const int bm = blockIdx.y * 128;
    const int bn = blockIdx.x * 128;

    // A-tile load mapping: 128 rows x 8 cols = 256 float4 (one per thread)
    const int aRow = tid >> 1;            // 0..127
    const int aCol = (tid & 1) << 2;      // 0 or 4
    // B-tile load mapping: 8 rows x 128 cols = 256 float4
    const int bRow = tid >> 5;            // 0..7
    const int bCol = (tid & 31) << 2;     // 0..124

    const float* Aptr = A + (size_t)(bm + aRow) * K + aCol;
    const float* Bptr = W + (size_t)bRow * N + bn + bCol;

    const int tx = tid & 15;              // 0..15  -> col group
    const int ty = tid >> 4;              // 0..15  -> row group
    const int mro = ty * 8;
    const int nco = tx * 8;

    float acc[8][8];
    #pragma unroll
    for (int i = 0; i < 8; i++)
        #pragma unroll
        for (int j = 0; j < 8; j++) acc[i][j] = 0.0f;

    for (int k0 = 0; k0 < K; k0 += 8) {
        float4 av = *(const float4*)Aptr;  Aptr += 8;
        float4 bv = *(const float4*)Bptr;  Bptr += (size_t)8 * N;

        __syncthreads();   // previous tile fully consumed
        As[aCol + 0][aRow] = av.x;
        As[aCol + 1][aRow] = av.y;
        As[aCol + 2][aRow] = av.z;
        As[aCol + 3][aRow] = av.w;
        *(float4*)&Bs[bRow][bCol] = bv;
        __syncthreads();

        #pragma unroll
        for (int kk = 0; kk < 8; kk++) {
            float a[8], b[8];
            *(float4*)&a[0] = *(const float4*)&As[kk][mro];
            *(float4*)&a[4] = *(const float4*)&As[kk][mro + 4];
            *(float4*)&b[0] = *(const float4*)&Bs[kk][nco];
            *(float4*)&b[4] = *(const float4*)&Bs[kk][nco + 4];
            #pragma unroll
            for (int i = 0; i < 8; i++)
                #pragma unroll
                for (int j = 0; j < 8; j++)
                    acc[i][j] = fmaf(a[i], b[j], acc[i][j]);
        }
    }

    // Epilogue: bias (+ReLU) (+mask-prev zeroing)
    const int row0 = bm + mro;
    const int col0 = bn + nco;
    float bv[8];
    #pragma unroll
    for (int j = 0; j < 8; j++) bv[j] = bias[col0 + j];

    #pragma unroll
    for (int i = 0; i < 8; i++) {
        size_t base = (size_t)(row0 + i) * N + col0;
        #pragma unroll
        for (int j = 0; j < 8; j++) {
            float v = acc[i][j] + bv[j];
            if (do_relu) v = fmaxf(v, 0.0f);
            if (mask != nullptr && mask[base + j] > 0.0f) v = 0.0f;
            C[base + j] = v;
        }
    }
}

// ---------------------------------------------------------------------------
// Per-token exact top-256-of-1024 by energy = h*h, via 4-pass MSB radix
// select on the uint bit pattern (monotone for nonnegative floats).
// One block (256 threads) per token. Output: h where kept, else 0.
// Tie handling: entries strictly above threshold always kept; entries equal
// to threshold kept in index order up to the remaining budget (ties at a
// positive threshold are measure-zero; ties at zero have h == 0 anyway).
// ---------------------------------------------------------------------------
__global__ __launch_bounds__(256)
void topk_mask_kernel(const float* __restrict__ H, float* __restrict__ out)
{
    const int tid = threadIdx.x;
    const size_t row = (size_t)blockIdx.x * HDIM;

    __shared__ unsigned ebits[HDIM];
    __shared__ unsigned hist[256];
    __shared__ unsigned sc[256];
    __shared__ unsigned s_pref, s_r;

    float4 hv = ((const float4*)(H + row))[tid];   // elements 4*tid .. 4*tid+3
    float e0 = hv.x * hv.x, e1 = hv.y * hv.y, e2 = hv.z * hv.z, e3 = hv.w * hv.w;
    unsigned v0 = __float_as_uint(e0);
    unsigned v1 = __float_as_uint(e1);
    unsigned v2 = __float_as_uint(e2);
    unsigned v3 = __float_as_uint(e3);
    ebits[4 * tid + 0] = v0;
    ebits[4 * tid + 1] = v1;
    ebits[4 * tid + 2] = v2;
    ebits[4 * tid + 3] = v3;
    if (tid == 0) { s_pref = 0u; s_r = KSEL; }
    __syncthreads();

    #pragma unroll
    for (int pass = 0; pass < 4; pass++) {
        const int shift = 24 - 8 * pass;
        const unsigned pref = s_pref;
        const unsigned r    = s_r;
        hist[tid] = 0u;
        __syncthreads();

        #pragma unroll
        for (int j = 0; j < 4; j++) {
            unsigned v = ebits[4 * tid + j];
            bool cand = (pass == 0) || ((v >> (shift + 8)) == (pref >> (shift + 8)));
            if (cand) atomicAdd(&hist[(v >> shift) & 0xFFu], 1u);
        }
        __syncthreads();

        // suffix-inclusive scan: sc[b] = sum_{b' >= b} hist[b']
        sc[tid] = hist[tid];
        __syncthreads();
        for (int off = 1; off < 256; off <<= 1) {
            unsigned add = (tid + off < 256) ? sc[tid + off] : 0u;
            __syncthreads();
            sc[tid] += add;
            __syncthreads();
        }

        unsigned above = (tid == 255) ? 0u : sc[tid + 1];
        if (sc[tid] >= r && above < r) {       // unique bin (suffix monotone)
            s_pref = pref | ((unsigned)tid << shift);
            s_r    = r - above;
        }
        __syncthreads();
    }

    const unsigned thr  = s_pref;   // exact bit pattern of 256th-largest energy
    const unsigned need = s_r;      // how many entries EQUAL to thr to keep

    // index-ordered rank among equals: per-thread local count + block scan
    unsigned vv[4] = {v0, v1, v2, v3};
    unsigned pos[4];
    unsigned myc = 0;
    #pragma unroll
    for (int j = 0; j < 4; j++) {
        pos[j] = myc;
        myc += (vv[j] == thr) ? 1u : 0u;
    }
    sc[tid] = myc;
    __syncthreads();
    for (int off = 1; off < 256; off <<= 1) {
        unsigned add = (tid >= off) ? sc[tid - off] : 0u;
        __syncthreads();
        sc[tid] += add;
        __syncthreads();
    }
    const unsigned base = sc[tid] - myc;   // exclusive prefix of equals

    float h[4] = {hv.x, hv.y, hv.z, hv.w};
    float o[4];
    #pragma unroll
    for (int j = 0; j < 4; j++) {
        bool keep = (vv[j] > thr) || (vv[j] == thr && (base + pos[j]) < need);
        o[j] = keep ? h[j] : 0.0f;
    }
    ((float4*)(out + row))[tid] = make_float4(o[0], o[1], o[2], o[3]);
}

// ---------------------------------------------------------------------------
// kernel_launch
// ---------------------------------------------------------------------------
extern "C" void kernel_launch(void* const* d_in, const int* in_sizes, int n_in,
                              void* d_out, int out_size)
{
    const float* x         = (const float*)d_in[0];
    const float* mask_prev = (const float*)d_in[1];

    // Disambiguate input ordering at runtime:
    //  interleaved (setup_inputs dict order): x, mask, [e_w i, e_b i, d_w i, d_b i] x4
    //  sequential  (signature order):         x, mask, e_w0..e_b3, d_w0..d_b3
    // in_sizes[4]: interleaved -> d_w0 = 1024*512 = 524288; sequential -> e_w1 = 262144
    const bool inter = (in_sizes[4] == HDIM * 512);

    const float *ew[4], *eb[4], *dw[4], *db[4];
    for (int i = 0; i < 4; i++) {
        if (inter) {
            ew[i] = (const float*)d_in[2 + 4 * i];
            eb[i] = (const float*)d_in[3 + 4 * i];
            dw[i] = (const float*)d_in[4 + 4 * i];
            db[i] = (const float*)d_in[5 + 4 * i];
        } else {
            ew[i] = (const float*)d_in[2 + 2 * i];
            eb[i] = (const float*)d_in[3 + 2 * i];
            dw[i] = (const float*)d_in[10 + 2 * i];
            db[i] = (const float*)d_in[11 + 2 * i];
        }
    }

    float *bufA = nullptr, *bufB = nullptr;
    cudaGetSymbolAddress((void**)&bufA, g_bufA);
    cudaGetSymbolAddress((void**)&bufB, g_bufB);

    const int M = MTOK;
    dim3 blk(256);

    // Encoder
    {
        dim3 g(512 / 128, M / 128);
        sgemm_kernel<<<g, blk>>>(x,    ew[0], eb[0], nullptr, bufA, M, 512, 512, 1);
        sgemm_kernel<<<g, blk>>>(bufA, ew[1], eb[1], nullptr, bufB, M, 512, 512, 1);
        sgemm_kernel<<<g, blk>>>(bufB, ew[2], eb[2], nullptr, bufA, M, 512, 512, 1);
    }
    {
        dim3 g(HDIM / 128, M / 128);
        // last encoder layer: no relu, fuse mask_prev exclusion
        sgemm_kernel<<<g, blk>>>(bufA, ew[3], eb[3], mask_prev, bufB, M, HDIM, 512, 0);
    }

    // Top-k (256 of 1024) sparsification: bufB (h) -> bufA (masked h)
    topk_mask_kernel<<<MTOK, 256>>>(bufB, bufA);

    // Decoder
    {
        dim3 g(512 / 128, M / 128);
        sgemm_kernel<<<g, blk>>>(bufA, dw[0], db[0], nullptr, bufB, M, 512, HDIM, 1);
        sgemm_kernel<<<g, blk>>>(bufB, dw[1], db[1], nullptr, bufA, M, 512, 512, 1);
        sgemm_kernel<<<g, blk>>>(bufA, dw[2], db[2], nullptr, bufB, M, 512, 512, 1);
        sgemm_kernel<<<g, blk>>>(bufB, dw[3], db[3], nullptr, (float*)d_out, M, 512, 512, 0);
    }
}

// round 7
// speedup vs baseline: 2.3939x; 2.3939x over previous
#include <cuda_runtime.h>
#include <cuda_fp16.h>
#include <cstdint>

#define MTOK   65536
#define HDIM   1024
#define KSEL   256

// ---------------------------------------------------------------------------
// Static scratch. Activations: splits of (value * 512), parts fp16.
// Weights: transposed [N,K] splits of (value * 512), parts fp16.
// ---------------------------------------------------------------------------
__device__ __half g_a0[(size_t)MTOK * HDIM];
__device__ __half g_a1[(size_t)MTOK * HDIM];
__device__ __half g_a2[(size_t)MTOK * HDIM];
__device__ __half g_b0[(size_t)MTOK * HDIM];
__device__ __half g_b1[(size_t)MTOK * HDIM];
__device__ __half g_b2[(size_t)MTOK * HDIM];
__device__ float  g_hF[(size_t)MTOK * HDIM];
#define WT_TOTAL 2621440
__device__ __half g_w0[WT_TOTAL];
__device__ __half g_w1[WT_TOTAL];
__device__ __half g_w2[WT_TOTAL];

// ---------------------------------------------------------------------------
// Helpers
// ---------------------------------------------------------------------------
__device__ __forceinline__ uint32_t smem_u32(const void* p) {
    uint32_t a;
    asm("{ .reg .u64 t; cvta.to.shared.u64 t, %1; cvt.u32.u64 %0, t; }" : "=r"(a) : "l"(p));
    return a;
}
__device__ __forceinline__ uint32_t lds32(uint32_t a) {
    uint32_t v;
    asm volatile("ld.shared.b32 %0, [%1];" : "=r"(v) : "r"(a));
    return v;
}
__device__ __forceinline__ void cp16(uint32_t dst, const void* src) {
    asm volatile("cp.async.cg.shared.global [%0], [%1], 16;" :: "r"(dst), "l"(src) : "memory");
}
__device__ __forceinline__ void mma16816(float* c, const uint32_t* a, uint32_t b0, uint32_t b1) {
    asm volatile(
        "mma.sync.aligned.m16n8k16.row.col.f32.f16.f16.f32 "
        "{%0,%1,%2,%3}, {%4,%5,%6,%7}, {%8,%9}, {%0,%1,%2,%3};"
        : "+f"(c[0]), "+f"(c[1]), "+f"(c[2]), "+f"(c[3])
        : "r"(a[0]), "r"(a[1]), "r"(a[2]), "r"(a[3]), "r"(b0), "r"(b1));
}
// D = A*B + 0  (fresh accumulator: no inherited C-chain truncation bias)
__device__ __forceinline__ void mma16816_z(float* d, const uint32_t* a, uint32_t b0, uint32_t b1) {
    asm volatile(
        "mma.sync.aligned.m16n8k16.row.col.f32.f16.f16.f32 "
        "{%0,%1,%2,%3}, {%4,%5,%6,%7}, {%8,%9}, {%10,%11,%12,%13};"
        : "=f"(d[0]), "=f"(d[1]), "=f"(d[2]), "=f"(d[3])
        : "r"(a[0]), "r"(a[1]), "r"(a[2]), "r"(a[3]), "r"(b0), "r"(b1),
          "f"(0.0f), "f"(0.0f), "f"(0.0f), "f"(0.0f));
}
__device__ __forceinline__ uint32_t pack_h2(__half a, __half b) {
    __half2 h2 = __halves2half2(a, b);
    return *reinterpret_cast<uint32_t*>(&h2);
}

// ---------------------------------------------------------------------------
// HMMA split-fp16 GEMM.  true C = act( 2^-18 * sum_t A_pa @ B_pb^T + bias )
// MODE 0 (encoder): 3 parts, 6 terms; per-k16 fresh-accumulator extraction +
//                   RN FADD folding (kills tensor-core C-chain truncation bias).
// MODE 1 (decoder): 2 parts, 3 terms; direct HW chaining (smooth path).
// CTA 128x128, 8 warps (2x4), warp tile 64x32, k-chunk 32, 3-stage cp.async.
// ---------------------------------------------------------------------------
template<int MODE>
__global__ __launch_bounds__(256, 1)
void gemm_hmma(const __half* __restrict__ A0, const __half* __restrict__ A1,
               const __half* __restrict__ A2,
               const __half* __restrict__ W0, const __half* __restrict__ W1,
               const __half* __restrict__ W2,
               const float* __restrict__ bias, const float* __restrict__ mask,
               __half* __restrict__ O0, __half* __restrict__ O1,
               __half* __restrict__ O2, float* __restrict__ OF,
               int N, int K, int relu)
{
    constexpr int NPA = (MODE == 0) ? 3 : 2;
    constexpr int NT  = (MODE == 0) ? 6 : 3;
    constexpr int NPARTS = 2 * NPA;
    constexpr uint32_t PART  = 10240;            // 128 rows * 80B (64 data + 16 pad)
    constexpr uint32_t STAGE = NPARTS * PART;
    constexpr int PA_[2][6] = {{0, 1, 0, 2, 1, 0}, {0, 1, 0, 0, 0, 0}};
    constexpr int PB_[2][6] = {{0, 0, 1, 0, 1, 2}, {0, 0, 1, 0, 0, 0}};

    extern __shared__ __align__(16) char smem_raw[];
    const uint32_t smb = smem_u32(smem_raw);

    const int tid    = threadIdx.x;
    const int wid    = tid >> 5;
    const int lane   = tid & 31;
    const int warp_m = wid >> 2;
    const int warp_n = wid & 3;
    const int g      = lane >> 2;
    const int tg     = lane & 3;
    const int bm     = blockIdx.y * 128;
    const int bn     = blockIdx.x * 128;
    const int C      = K >> 5;

    const __half* Pp[6];
    Pp[0] = A0; Pp[1] = A1; Pp[2] = (MODE == 0) ? A2 : W0;
    if (MODE == 0) { Pp[3] = W0; Pp[4] = W1; Pp[5] = W2; }
    else           { Pp[3] = W1; }

    auto load_stage = [&](int c, int slot) {
        const uint32_t sbase = smb + (uint32_t)slot * STAGE;
        int i = tid;
        #pragma unroll
        for (int s = 0; s < NPARTS * 2; s++, i += 256) {
            int p   = i >> 9;
            int j   = i & 511;
            int row = j >> 2;
            int ch  = j & 3;
            const __half* src = Pp[p]
                              + (size_t)((p < NPA ? bm : bn) + row) * K + c * 32 + ch * 8;
            uint32_t dst = sbase + (uint32_t)p * PART
                         + (uint32_t)row * 80u + (uint32_t)ch * 16u;
            cp16(dst, src);
        }
        asm volatile("cp.async.commit_group;" ::: "memory");
    };

    load_stage(0, 0);
    load_stage(1, 1);
    load_stage(2, 2);

    float acc[4][4][4];
    #pragma unroll
    for (int i = 0; i < 4; i++)
        #pragma unroll
        for (int j = 0; j < 4; j++)
            #pragma unroll
            for (int e = 0; e < 4; e++) acc[i][j][e] = 0.0f;

    const uint32_t aRowOff = (uint32_t)(warp_m * 64 + g) * 80u + (uint32_t)tg * 4u;
    const uint32_t bRowOff = (uint32_t)(warp_n * 32 + g) * 80u + (uint32_t)tg * 4u;

    for (int c = 0; c < C; c++) {
        if (c + 2 < C)      asm volatile("cp.async.wait_group 2;" ::: "memory");
        else if (c + 1 < C) asm volatile("cp.async.wait_group 1;" ::: "memory");
        else                asm volatile("cp.async.wait_group 0;" ::: "memory");
        __syncthreads();

        const uint32_t sb0 = smb + (uint32_t)(c % 3) * STAGE;

        if (MODE == 0) {
            // Encoder: per k16-half, all terms into a FRESH accumulator, then
            // fold into master with RN FADDs (unbiased).
            #pragma unroll
            for (int kh = 0; kh < 2; kh++) {
                float tmp[4][4][4];
                #pragma unroll
                for (int t = 0; t < NT; t++) {
                    const uint32_t aBase = sb0 + (uint32_t)PA_[0][t] * PART + aRowOff;
                    const uint32_t bBase = sb0 + (uint32_t)(NPA + PB_[0][t]) * PART + bRowOff;
                    uint32_t af[4][4];
                    #pragma unroll
                    for (int mt = 0; mt < 4; mt++) {
                        uint32_t a = aBase + (uint32_t)mt * (16u * 80u) + (uint32_t)kh * 32u;
                        af[mt][0] = lds32(a);
                        af[mt][1] = lds32(a + 8u * 80u);
                        af[mt][2] = lds32(a + 16u);
                        af[mt][3] = lds32(a + 8u * 80u + 16u);
                    }
                    #pragma unroll
                    for (int nt = 0; nt < 4; nt++) {
                        uint32_t b  = bBase + (uint32_t)nt * (8u * 80u) + (uint32_t)kh * 32u;
                        uint32_t b0 = lds32(b);
                        uint32_t b1 = lds32(b + 16u);
                        #pragma unroll
                        for (int mt = 0; mt < 4; mt++) {
                            if (t == 0) mma16816_z(tmp[mt][nt], af[mt], b0, b1);
                            else        mma16816(tmp[mt][nt], af[mt], b0, b1);
                        }
                    }
                }
                #pragma unroll
                for (int mt = 0; mt < 4; mt++)
                    #pragma unroll
                    for (int nt = 0; nt < 4; nt++)
                        #pragma unroll
                        for (int e = 0; e < 4; e++)
                            acc[mt][nt][e] += tmp[mt][nt][e];
            }
        } else {
            // Decoder: direct HW chaining (bias irrelevant on smooth path)
            #pragma unroll
            for (int t = 0; t < NT; t++) {
                const uint32_t aBase = sb0 + (uint32_t)PA_[1][t] * PART + aRowOff;
                const uint32_t bBase = sb0 + (uint32_t)(NPA + PB_[1][t]) * PART + bRowOff;
                #pragma unroll
                for (int kh = 0; kh < 2; kh++) {
                    uint32_t af[4][4];
                    #pragma unroll
                    for (int mt = 0; mt < 4; mt++) {
                        uint32_t a = aBase + (uint32_t)mt * (16u * 80u) + (uint32_t)kh * 32u;
                        af[mt][0] = lds32(a);
                        af[mt][1] = lds32(a + 8u * 80u);
                        af[mt][2] = lds32(a + 16u);
                        af[mt][3] = lds32(a + 8u * 80u + 16u);
                    }
                    #pragma unroll
                    for (int nt = 0; nt < 4; nt++) {
                        uint32_t b  = bBase + (uint32_t)nt * (8u * 80u) + (uint32_t)kh * 32u;
                        uint32_t b0 = lds32(b);
                        uint32_t b1 = lds32(b + 16u);
                        #pragma unroll
                        for (int mt = 0; mt < 4; mt++)
                            mma16816(acc[mt][nt], af[mt], b0, b1);
                    }
                }
            }
        }
        __syncthreads();
        if (c + 3 < C) load_stage(c + 3, (c + 3) % 3);
    }

    // ---- epilogue ----
    const float SCL = 1.0f / 262144.0f;       // 2^-18
    #pragma unroll
    for (int mt = 0; mt < 4; mt++) {
        #pragma unroll
        for (int nt = 0; nt < 4; nt++) {
            const int row = bm + warp_m * 64 + mt * 16 + g;
            const int col = bn + warp_n * 32 + nt * 8 + tg * 2;
            const float bz0 = __ldg(bias + col);
            const float bz1 = __ldg(bias + col + 1);
            float v0 = acc[mt][nt][0] * SCL + bz0;
            float v1 = acc[mt][nt][1] * SCL + bz1;
            float v2 = acc[mt][nt][2] * SCL + bz0;   // row + 8
            float v3 = acc[mt][nt][3] * SCL + bz1;
            if (relu) {
                v0 = fmaxf(v0, 0.f); v1 = fmaxf(v1, 0.f);
                v2 = fmaxf(v2, 0.f); v3 = fmaxf(v3, 0.f);
            }
            const size_t i0 = (size_t)row * N + col;
            const size_t i1 = (size_t)(row + 8) * N + col;
            if (OF) {
                if (mask) {
                    const float2 m0 = *(const float2*)(mask + i0);
                    const float2 m1 = *(const float2*)(mask + i1);
                    if (m0.x > 0.f) v0 = 0.f;
                    if (m0.y > 0.f) v1 = 0.f;
                    if (m1.x > 0.f) v2 = 0.f;
                    if (m1.y > 0.f) v3 = 0.f;
                }
                *(float2*)(OF + i0) = make_float2(v0, v1);
                *(float2*)(OF + i1) = make_float2(v2, v3);
            } else {
                float s0 = v0 * 512.f, s1 = v1 * 512.f;
                float s2 = v2 * 512.f, s3 = v3 * 512.f;
                __half h0 = __float2half_rn(s0), h1 = __float2half_rn(s1);
                __half h2 = __float2half_rn(s2), h3 = __float2half_rn(s3);
                float r0 = s0 - __half2float(h0), r1 = s1 - __half2float(h1);
                float r2 = s2 - __half2float(h2), r3 = s3 - __half2float(h3);
                __half q0 = __float2half_rn(r0), q1 = __float2half_rn(r1);
                __half q2 = __float2half_rn(r2), q3 = __float2half_rn(r3);
                *(uint32_t*)(O0 + i0) = pack_h2(h0, h1);
                *(uint32_t*)(O0 + i1) = pack_h2(h2, h3);
                *(uint32_t*)(O1 + i0) = pack_h2(q0, q1);
                *(uint32_t*)(O1 + i1) = pack_h2(q2, q3);
                if (MODE == 0) {
                    __half u0 = __float2half_rn(r0 - __half2float(q0));
                    __half u1 = __float2half_rn(r1 - __half2float(q1));
                    __half u2 = __float2half_rn(r2 - __half2float(q2));
                    __half u3 = __float2half_rn(r3 - __half2float(q3));
                    *(uint32_t*)(O2 + i0) = pack_h2(u0, u1);
                    *(uint32_t*)(O2 + i1) = pack_h2(u2, u3);
                }
            }
        }
    }
}

// ---------------------------------------------------------------------------
// x -> 3-way fp16 split (scaled by 512)
// ---------------------------------------------------------------------------
__global__ void conv_x_kernel(const float* __restrict__ x,
                              __half* __restrict__ o0, __half* __restrict__ o1,
                              __half* __restrict__ o2)
{
    size_t i = ((size_t)blockIdx.x * blockDim.x + threadIdx.x) * 2;
    float x0 = x[i] * 512.f, x1 = x[i + 1] * 512.f;
    __half h0 = __float2half_rn(x0), h1 = __float2half_rn(x1);
    float r0 = x0 - __half2float(h0), r1 = x1 - __half2float(h1);
    __half q0 = __float2half_rn(r0), q1 = __float2half_rn(r1);
    __half u0 = __float2half_rn(r0 - __half2float(q0));
    __half u1 = __float2half_rn(r1 - __half2float(q1));
    *(uint32_t*)(o0 + i) = pack_h2(h0, h1);
    *(uint32_t*)(o1 + i) = pack_h2(q0, q1);
    *(uint32_t*)(o2 + i) = pack_h2(u0, u1);
}

// ---------------------------------------------------------------------------
// W[K,N] -> transposed split parts (scaled by 512): o[n*K+k]; o2 optional
// ---------------------------------------------------------------------------
__global__ void conv_w_kernel(const float* __restrict__ W,
                              __half* __restrict__ o0, __half* __restrict__ o1,
                              __half* __restrict__ o2,
                              int kshift, int N)
{
    int idx = blockIdx.x * blockDim.x + threadIdx.x;
    int n = idx >> kshift;
    int k = idx & ((1 << kshift) - 1);
    float w = W[(size_t)k * N + n] * 512.f;
    __half h = __float2half_rn(w);
    float r = w - __half2float(h);
    __half q = __float2half_rn(r);
    o0[idx] = h;
    o1[idx] = q;
    if (o2) o2[idx] = __float2half_rn(r - __half2float(q));
}

// ---------------------------------------------------------------------------
// Exact per-token top-256-of-1024 by h^2 (radix select on float bit pattern).
// Output = 2-way fp16 split (scaled by 512) of (kept ? h : 0).
// ---------------------------------------------------------------------------
__global__ __launch_bounds__(256)
void topk_mask_kernel(const float* __restrict__ H,
                      __half* __restrict__ o0, __half* __restrict__ o1)
{
    const int tid = threadIdx.x;
    const size_t row = (size_t)blockIdx.x * HDIM;

    __shared__ unsigned ebits[HDIM];
    __shared__ unsigned hist[256];
    __shared__ unsigned sc[256];
    __shared__ unsigned s_pref, s_r;

    float4 hv = ((const float4*)(H + row))[tid];
    unsigned v0 = __float_as_uint(hv.x * hv.x);
    unsigned v1 = __float_as_uint(hv.y * hv.y);
    unsigned v2 = __float_as_uint(hv.z * hv.z);
    unsigned v3 = __float_as_uint(hv.w * hv.w);
    ebits[4 * tid + 0] = v0; ebits[4 * tid + 1] = v1;
    ebits[4 * tid + 2] = v2; ebits[4 * tid + 3] = v3;
    if (tid == 0) { s_pref = 0u; s_r = KSEL; }
    __syncthreads();

    #pragma unroll
    for (int pass = 0; pass < 4; pass++) {
        const int shift = 24 - 8 * pass;
        const unsigned pref = s_pref;
        const unsigned r    = s_r;
        hist[tid] = 0u;
        __syncthreads();
        #pragma unroll
        for (int j = 0; j < 4; j++) {
            unsigned v = ebits[4 * tid + j];
            bool cand = (pass == 0) || ((v >> (shift + 8)) == (pref >> (shift + 8)));
            if (cand) atomicAdd(&hist[(v >> shift) & 0xFFu], 1u);
        }
        __syncthreads();
        sc[tid] = hist[tid];
        __syncthreads();
        for (int off = 1; off < 256; off <<= 1) {
            unsigned add = (tid + off < 256) ? sc[tid + off] : 0u;
            __syncthreads();
            sc[tid] += add;
            __syncthreads();
        }
        unsigned above = (tid == 255) ? 0u : sc[tid + 1];
        if (sc[tid] >= r && above < r) {
            s_pref = pref | ((unsigned)tid << shift);
            s_r    = r - above;
        }
        __syncthreads();
    }

    const unsigned thr  = s_pref;
    const unsigned need = s_r;

    unsigned vv[4] = {v0, v1, v2, v3};
    unsigned pos[4];
    unsigned myc = 0;
    #pragma unroll
    for (int j = 0; j < 4; j++) { pos[j] = myc; myc += (vv[j] == thr) ? 1u : 0u; }
    sc[tid] = myc;
    __syncthreads();
    for (int off = 1; off < 256; off <<= 1) {
        unsigned add = (tid >= off) ? sc[tid - off] : 0u;
        __syncthreads();
        sc[tid] += add;
        __syncthreads();
    }
    const unsigned base = sc[tid] - myc;

    float h[4] = {hv.x, hv.y, hv.z, hv.w};
    uint32_t w0[2], w1[2];
    #pragma unroll
    for (int e = 0; e < 2; e++) {
        __half hh[2], ll[2];
        #pragma unroll
        for (int q = 0; q < 2; q++) {
            int j = 2 * e + q;
            bool keep = (vv[j] > thr) || (vv[j] == thr && (base + pos[j]) < need);
            float o = (keep ? h[j] : 0.0f) * 512.f;
            hh[q] = __float2half_rn(o);
            ll[q] = __float2half_rn(o - __half2float(hh[q]));
        }
        w0[e] = pack_h2(hh[0], hh[1]);
        w1[e] = pack_h2(ll[0], ll[1]);
    }
    ((uint2*)(o0 + row))[tid] = make_uint2(w0[0], w0[1]);
    ((uint2*)(o1 + row))[tid] = make_uint2(w1[0], w1[1]);
}

// ---------------------------------------------------------------------------
// kernel_launch
// ---------------------------------------------------------------------------
extern "C" void kernel_launch(void* const* d_in, const int* in_sizes, int n_in,
                              void* d_out, int out_size)
{
    const float* x         = (const float*)d_in[0];
    const float* mask_prev = (const float*)d_in[1];
    const bool inter = (in_sizes[4] == HDIM * 512);

    const float *ew[4], *eb[4], *dw[4], *db[4];
    for (int i = 0; i < 4; i++) {
        if (inter) {
            ew[i] = (const float*)d_in[2 + 4 * i]; eb[i] = (const float*)d_in[3 + 4 * i];
            dw[i] = (const float*)d_in[4 + 4 * i]; db[i] = (const float*)d_in[5 + 4 * i];
        } else {
            ew[i] = (const float*)d_in[2 + 2 * i]; eb[i] = (const float*)d_in[3 + 2 * i];
            dw[i] = (const float*)d_in[10 + 2 * i]; db[i] = (const float*)d_in[11 + 2 * i];
        }
    }

    __half *a0, *a1, *a2, *b0, *b1, *b2, *w0, *w1, *w2;
    float* hF;
    cudaGetSymbolAddress((void**)&a0, g_a0); cudaGetSymbolAddress((void**)&a1, g_a1);
    cudaGetSymbolAddress((void**)&a2, g_a2); cudaGetSymbolAddress((void**)&b0, g_b0);
    cudaGetSymbolAddress((void**)&b1, g_b1); cudaGetSymbolAddress((void**)&b2, g_b2);
    cudaGetSymbolAddress((void**)&w0, g_w0); cudaGetSymbolAddress((void**)&w1, g_w1);
    cudaGetSymbolAddress((void**)&w2, g_w2); cudaGetSymbolAddress((void**)&hF, g_hF);

    const int SM_ENC = 3 * 6 * 10240;   // 184320
    const int SM_DEC = 3 * 4 * 10240;   // 122880
    cudaFuncSetAttribute(gemm_hmma<0>, cudaFuncAttributeMaxDynamicSharedMemorySize, SM_ENC);
    cudaFuncSetAttribute(gemm_hmma<1>, cudaFuncAttributeMaxDynamicSharedMemorySize, SM_DEC);

    // ---- weight conversion (transpose + split, scale 512) ----
    struct { const float* w; int K, N; size_t off; int np; } L[8] = {
        {ew[0], 512, 512, 0, 3},        {ew[1], 512, 512, 262144, 3},
        {ew[2], 512, 512, 524288, 3},   {ew[3], 512, 1024, 786432, 3},
        {dw[0], 1024, 512, 1310720, 2}, {dw[1], 512, 512, 1835008, 2},
        {dw[2], 512, 512, 2097152, 2},  {dw[3], 512, 512, 2359296, 2}};
    for (int l = 0; l < 8; l++) {
        int tot = L[l].K * L[l].N;
        int ksh = (L[l].K == 1024) ? 10 : 9;
        conv_w_kernel<<<tot / 256, 256>>>(L[l].w, w0 + L[l].off, w1 + L[l].off,
                                          (L[l].np == 3) ? (w2 + L[l].off) : nullptr,
                                          ksh, L[l].N);
    }
    // ---- x split ----
    conv_x_kernel<<<(MTOK * 512 / 2) / 256, 256>>>(x, a0, a1, a2);

    const dim3 blk(256);
    // ---- encoder (3-way split, 6 terms, debiased accumulation) ----
    gemm_hmma<0><<<dim3(4, 512), blk, SM_ENC>>>(a0, a1, a2,
        w0 + L[0].off, w1 + L[0].off, w2 + L[0].off, eb[0], nullptr,
        b0, b1, b2, nullptr, 512, 512, 1);
    gemm_hmma<0><<<dim3(4, 512), blk, SM_ENC>>>(b0, b1, b2,
        w0 + L[1].off, w1 + L[1].off, w2 + L[1].off, eb[1], nullptr,
        a0, a1, a2, nullptr, 512, 512, 1);
    gemm_hmma<0><<<dim3(4, 512), blk, SM_ENC>>>(a0, a1, a2,
        w0 + L[2].off, w1 + L[2].off, w2 + L[2].off, eb[2], nullptr,
        b0, b1, b2, nullptr, 512, 512, 1);
    gemm_hmma<0><<<dim3(8, 512), blk, SM_ENC>>>(b0, b1, b2,
        w0 + L[3].off, w1 + L[3].off, w2 + L[3].off, eb[3], mask_prev,
        nullptr, nullptr, nullptr, hF, 1024, 512, 0);

    // ---- top-k sparsify -> split decoder input ----
    topk_mask_kernel<<<MTOK, 256>>>(hF, a0, a1);

    // ---- decoder (2-way split, 3 terms) ----
    gemm_hmma<1><<<dim3(4, 512), blk, SM_DEC>>>(a0, a1, nullptr,
        w0 + L[4].off, w1 + L[4].off, nullptr, db[0], nullptr,
        b0, b1, nullptr, nullptr, 512, 1024, 1);
    gemm_hmma<1><<<dim3(4, 512), blk, SM_DEC>>>(b0, b1, nullptr,
        w0 + L[5].off, w1 + L[5].off, nullptr, db[1], nullptr,
        a0, a1, nullptr, nullptr, 512, 512, 1);
    gemm_hmma<1><<<dim3(4, 512), blk, SM_DEC>>>(a0, a1, nullptr,
        w0 + L[6].off, w1 + L[6].off, nullptr, db[2], nullptr,
        b0, b1, nullptr, nullptr, 512, 512, 1);
    gemm_hmma<1><<<dim3(4, 512), blk, SM_DEC>>>(b0, b1, nullptr,
        w0 + L[7].off, w1 + L[7].off, nullptr, db[3], nullptr,
        nullptr, nullptr, nullptr, (float*)d_out, 512, 512, 0);
}